// round 1
// baseline (speedup 1.0000x reference)
#include <cuda_runtime.h>
#include <math.h>

#define Bc 8
#define Sc 2048
#define Dc 1024
#define Hc 4
#define HDc 256
#define BLKS_PER_B 64            // S / 32 rows-per-block
#define NBLK (Bc * BLKS_PER_B)   // 512 stats blocks

// ---------------- scratch (static device memory; no allocation) -------------
__device__ float4 g_rowstats[Bc * Sc];              // (mu_t, rstd_t, mu_i, rstd_i)
__device__ float4 g_partial4[NBLK * 512];           // per-block partial sums (t | i), 4 MB
__device__ float  g_simpart[NBLK];
__device__ float  g_sums[Bc * 2048];                // text_global | image_global (already /S)
__device__ float  g_globalsim[Bc];
__device__ float  g_gates[Bc * Hc * HDc];
__device__ float  g_gate[Bc];

// ---------------- block reduction of 4 floats, broadcast result -------------
__device__ __forceinline__ float4 blockReduce4(float4 v, int buf) {
    __shared__ float4 sh[2][8];
    const int lane = threadIdx.x & 31, warp = threadIdx.x >> 5;
#pragma unroll
    for (int o = 16; o > 0; o >>= 1) {
        v.x += __shfl_down_sync(0xffffffffu, v.x, o);
        v.y += __shfl_down_sync(0xffffffffu, v.y, o);
        v.z += __shfl_down_sync(0xffffffffu, v.z, o);
        v.w += __shfl_down_sync(0xffffffffu, v.w, o);
    }
    if (lane == 0) sh[buf][warp] = v;
    __syncthreads();
    if (warp == 0) {
        v = (lane < 8) ? sh[buf][lane] : make_float4(0.f, 0.f, 0.f, 0.f);
#pragma unroll
        for (int o = 4; o > 0; o >>= 1) {
            v.x += __shfl_down_sync(0xffffffffu, v.x, o);
            v.y += __shfl_down_sync(0xffffffffu, v.y, o);
            v.z += __shfl_down_sync(0xffffffffu, v.z, o);
            v.w += __shfl_down_sync(0xffffffffu, v.w, o);
        }
        if (lane == 0) sh[buf][0] = v;
    }
    __syncthreads();
    return sh[buf][0];
}

// ---------------- pass 1: per-row LN stats + cosine sim + batch partials ----
__global__ void __launch_bounds__(256) k_stats(
    const float* __restrict__ xt, const float* __restrict__ xi,
    const float* __restrict__ ltw, const float* __restrict__ ltb,
    const float* __restrict__ liw, const float* __restrict__ lib)
{
    const int blk = blockIdx.x;            // 0..511
    const int b   = blk >> 6;              // / BLKS_PER_B
    const int s0  = (blk & 63) << 5;       // 32 rows per block
    const int t   = threadIdx.x;

    const float4 wt = reinterpret_cast<const float4*>(ltw)[t];
    const float4 bt = reinterpret_cast<const float4*>(ltb)[t];
    const float4 wi = reinterpret_cast<const float4*>(liw)[t];
    const float4 bi = reinterpret_cast<const float4*>(lib)[t];
    const float4* xt4 = reinterpret_cast<const float4*>(xt);
    const float4* xi4 = reinterpret_cast<const float4*>(xi);

    float4 at = make_float4(0.f, 0.f, 0.f, 0.f);
    float4 ai = make_float4(0.f, 0.f, 0.f, 0.f);
    float sim_acc = 0.f;
    const float invD = 1.0f / (float)Dc;

    for (int r = 0; r < 32; r++) {
        const int row = b * Sc + s0 + r;
        const int idx = row * (Dc / 4) + t;
        const float4 a = xt4[idx];
        const float4 c = xi4[idx];

        float4 st;
        st.x = a.x + a.y + a.z + a.w;
        st.y = a.x*a.x + a.y*a.y + a.z*a.z + a.w*a.w;
        st.z = c.x + c.y + c.z + c.w;
        st.w = c.x*c.x + c.y*c.y + c.z*c.z + c.w*c.w;
        st = blockReduce4(st, 0);

        const float mut = st.x * invD;
        const float rt  = rsqrtf(fmaxf(st.y * invD - mut * mut, 0.f) + 1e-5f);
        const float mui = st.z * invD;
        const float ri  = rsqrtf(fmaxf(st.w * invD - mui * mui, 0.f) + 1e-5f);

        float4 tn, cn;
        tn.x = (a.x - mut) * rt * wt.x + bt.x;
        tn.y = (a.y - mut) * rt * wt.y + bt.y;
        tn.z = (a.z - mut) * rt * wt.z + bt.z;
        tn.w = (a.w - mut) * rt * wt.w + bt.w;
        cn.x = (c.x - mui) * ri * wi.x + bi.x;
        cn.y = (c.y - mui) * ri * wi.y + bi.y;
        cn.z = (c.z - mui) * ri * wi.z + bi.z;
        cn.w = (c.w - mui) * ri * wi.w + bi.w;

        at.x += tn.x; at.y += tn.y; at.z += tn.z; at.w += tn.w;
        ai.x += cn.x; ai.y += cn.y; ai.z += cn.z; ai.w += cn.w;

        float4 d;
        d.x = tn.x*cn.x + tn.y*cn.y + tn.z*cn.z + tn.w*cn.w;   // t . i
        d.y = tn.x*tn.x + tn.y*tn.y + tn.z*tn.z + tn.w*tn.w;   // t . t
        d.z = cn.x*cn.x + cn.y*cn.y + cn.z*cn.z + cn.w*cn.w;   // i . i
        d.w = 0.f;
        d = blockReduce4(d, 1);

        if (t == 0) g_rowstats[row] = make_float4(mut, rt, mui, ri);

        const float tno = fmaxf(sqrtf(d.y), 1e-6f);
        const float ino = fmaxf(sqrtf(d.z), 1e-6f);
        sim_acc += d.x / (tno * ino);
    }

    g_partial4[blk * 512 + t]       = at;
    g_partial4[blk * 512 + 256 + t] = ai;
    if (t == 0) g_simpart[blk] = sim_acc;
}

// ---------------- pass 2: fold 64 partials per batch (deterministic) --------
__global__ void __launch_bounds__(256) k_reduce()
{
    const int j = blockIdx.x * 256 + threadIdx.x;  // grid 64 -> 16384 slots
    const int b = j >> 11;
    const int slot = j & 2047;
    const float* gp = reinterpret_cast<const float*>(g_partial4);
    float s = 0.f;
#pragma unroll 8
    for (int p = 0; p < BLKS_PER_B; p++)
        s += gp[(b * BLKS_PER_B + p) * 2048 + slot];
    g_sums[j] = s * (1.0f / (float)Sc);            // already divided by S

    if (j < Bc) {
        float ss = 0.f;
        for (int p = 0; p < BLKS_PER_B; p++) ss += g_simpart[j * BLKS_PER_B + p];
        g_globalsim[j] = ss * (1.0f / (float)Sc);
    }
}

// ---------------- pass 3: gates = relu(Wa@tg + Wq@ig + biases + sim_feat) ---
__global__ void __launch_bounds__(256) k_gates(
    const float* __restrict__ Wa, const float* __restrict__ Wab,
    const float* __restrict__ Wq, const float* __restrict__ Wqb,
    const float* __restrict__ simw, const float* __restrict__ simb)
{
    __shared__ float tg[1024], ig[1024];
    const int b = blockIdx.x >> 2, h = blockIdx.x & 3;
    const int tid = threadIdx.x;
    for (int d = tid; d < 1024; d += 256) {
        tg[d] = g_sums[b * 2048 + d];
        ig[d] = g_sums[b * 2048 + 1024 + d];
    }
    __syncthreads();

    const float gsim = g_globalsim[b];
    const int warp = tid >> 5, lane = tid & 31;
    const float4* tg4 = reinterpret_cast<const float4*>(tg);
    const float4* ig4 = reinterpret_cast<const float4*>(ig);

    for (int k = warp; k < HDc; k += 8) {
        const float4* wa = reinterpret_cast<const float4*>(Wa + (h * HDc + k) * Dc);
        const float4* wq = reinterpret_cast<const float4*>(Wq + (h * HDc + k) * Dc);
        float da = 0.f, dq = 0.f;
#pragma unroll
        for (int m = 0; m < 8; m++) {
            const int i4 = lane + 32 * m;
            const float4 a = wa[i4], q = wq[i4];
            const float4 tv = tg4[i4], iv = ig4[i4];
            da += a.x*tv.x + a.y*tv.y + a.z*tv.z + a.w*tv.w;
            dq += q.x*iv.x + q.y*iv.y + q.z*iv.z + q.w*iv.w;
        }
#pragma unroll
        for (int o = 16; o > 0; o >>= 1) {
            da += __shfl_down_sync(0xffffffffu, da, o);
            dq += __shfl_down_sync(0xffffffffu, dq, o);
        }
        if (lane == 0) {
            const float gate = da + Wab[h * HDc + k] + dq + Wqb[h * HDc + k]
                             + gsim * simw[k] + simb[k];
            g_gates[b * 1024 + h * HDc + k] = fmaxf(gate, 0.f);
        }
    }
}

// ---------------- pass 4: final scalar gate per batch -----------------------
__global__ void __launch_bounds__(256) k_fc(
    const float* __restrict__ fcw, const float* __restrict__ fcb)
{
    const int b = blockIdx.x, tid = threadIdx.x;
    float acc = 0.f;
#pragma unroll
    for (int k = tid; k < 1024; k += 256) acc += g_gates[b * 1024 + k] * fcw[k];
    __shared__ float sh[8];
#pragma unroll
    for (int o = 16; o > 0; o >>= 1) acc += __shfl_down_sync(0xffffffffu, acc, o);
    if ((tid & 31) == 0) sh[tid >> 5] = acc;
    __syncthreads();
    if (tid == 0) {
        float s = 0.f;
#pragma unroll
        for (int w = 0; w < 8; w++) s += sh[w];
        g_gate[b] = 1.0f / (1.0f + expf(-(s + fcb[0])));
    }
}

// ---------------- pass 5: out = g*LN(t) + (1-g)*LN(i) -----------------------
__global__ void __launch_bounds__(256) k_out(
    const float* __restrict__ xt, const float* __restrict__ xi,
    const float* __restrict__ ltw, const float* __restrict__ ltb,
    const float* __restrict__ liw, const float* __restrict__ lib,
    float* __restrict__ out)
{
    const int t = threadIdx.x;
    const float4 wt = reinterpret_cast<const float4*>(ltw)[t];
    const float4 bt = reinterpret_cast<const float4*>(ltb)[t];
    const float4 wi = reinterpret_cast<const float4*>(liw)[t];
    const float4 bi = reinterpret_cast<const float4*>(lib)[t];
    const float4* xt4 = reinterpret_cast<const float4*>(xt);
    const float4* xi4 = reinterpret_cast<const float4*>(xi);
    float4* o4 = reinterpret_cast<float4*>(out);

    const int row0 = blockIdx.x * 4;
#pragma unroll
    for (int r = 0; r < 4; r++) {
        const int row = row0 + r;
        const float4 rs = g_rowstats[row];
        const float g  = g_gate[row >> 11];
        const float gm = 1.0f - g;
        const int idx  = row * 256 + t;
        const float4 a = xt4[idx];
        const float4 c = xi4[idx];
        float4 o;
        o.x = g * ((a.x - rs.x) * rs.y * wt.x + bt.x) + gm * ((c.x - rs.z) * rs.w * wi.x + bi.x);
        o.y = g * ((a.y - rs.x) * rs.y * wt.y + bt.y) + gm * ((c.y - rs.z) * rs.w * wi.y + bi.y);
        o.z = g * ((a.z - rs.x) * rs.y * wt.z + bt.z) + gm * ((c.z - rs.z) * rs.w * wi.z + bi.z);
        o.w = g * ((a.w - rs.x) * rs.y * wt.w + bt.w) + gm * ((c.w - rs.z) * rs.w * wi.w + bi.w);
        o4[idx] = o;
    }
}

// ---------------- launch -----------------------------------------------------
extern "C" void kernel_launch(void* const* d_in, const int* in_sizes, int n_in,
                              void* d_out, int out_size)
{
    const float* xt   = (const float*)d_in[0];
    const float* xi   = (const float*)d_in[1];
    const float* ltw  = (const float*)d_in[2];
    const float* ltb  = (const float*)d_in[3];
    const float* liw  = (const float*)d_in[4];
    const float* lib  = (const float*)d_in[5];
    const float* Wa   = (const float*)d_in[6];
    const float* Wab  = (const float*)d_in[7];
    const float* Wq   = (const float*)d_in[8];
    const float* Wqb  = (const float*)d_in[9];
    const float* simw = (const float*)d_in[10];
    const float* simb = (const float*)d_in[11];
    const float* fcw  = (const float*)d_in[12];
    const float* fcb  = (const float*)d_in[13];
    float* out = (float*)d_out;

    k_stats <<<NBLK, 256>>>(xt, xi, ltw, ltb, liw, lib);
    k_reduce<<<64, 256>>>();
    k_gates <<<Bc * Hc, 256>>>(Wa, Wab, Wq, Wqb, simw, simb);
    k_fc    <<<Bc, 256>>>(fcw, fcb);
    k_out   <<<(Bc * Sc) / 4, 256>>>(xt, xi, ltw, ltb, liw, lib, out);
}

// round 2
// speedup vs baseline: 2.2953x; 2.2953x over previous
#include <cuda_runtime.h>
#include <math.h>

#define Bc 8
#define Sc 2048
#define Dc 1024
#define Hc 4
#define HDc 256
#define ROWS_PER_BLK 32
#define NBLK ((Bc * Sc) / ROWS_PER_BLK)   // 512

// ---------------- scratch (static device memory; no allocation) -------------
__device__ float4 g_rowstats[Bc * Sc];      // (mu_t, rstd_t, mu_i, rstd_i)
__device__ float  g_partial[NBLK * 2048];   // per-block sum of tn | in (4 MB)
__device__ float  g_simpart[NBLK];
__device__ float  g_sums[Bc * 2048];        // text_global | image_global (already /S)
__device__ float  g_globalsim[Bc];
__device__ float  g_gates[Bc * Hc * HDc];
__device__ float  g_gate[Bc];

__device__ __forceinline__ float bfly(float v) {
#pragma unroll
    for (int o = 16; o > 0; o >>= 1) v += __shfl_xor_sync(0xffffffffu, v, o);
    return v;
}

// ---------------- pass 1: warp-per-row LN stats + sim + batch partials ------
__global__ void __launch_bounds__(256, 1) k_stats(
    const float* __restrict__ xt, const float* __restrict__ xi,
    const float* __restrict__ ltw, const float* __restrict__ ltb,
    const float* __restrict__ liw, const float* __restrict__ lib)
{
    __shared__ float sm[8192];   // [wt|bt|wi|bi] during loop, 4 combine slices after
    __shared__ float s_sim[8];

    const int tid = threadIdx.x, lane = tid & 31, warp = tid >> 5;

    for (int j = tid; j < 1024; j += 256) {
        sm[j]        = ltw[j];
        sm[1024 + j] = ltb[j];
        sm[2048 + j] = liw[j];
        sm[3072 + j] = lib[j];
    }
    __syncthreads();

    const int blk  = blockIdx.x;
    const int row0 = blk * ROWS_PER_BLK + warp * 4;

    const float4* xt4 = reinterpret_cast<const float4*>(xt);
    const float4* xi4 = reinterpret_cast<const float4*>(xi);

    float4 vt[8], vi[8];
#pragma unroll
    for (int g = 0; g < 8; g++) {
        vt[g] = make_float4(0.f, 0.f, 0.f, 0.f);
        vi[g] = make_float4(0.f, 0.f, 0.f, 0.f);
    }
    float sim_acc = 0.f;

    for (int r = 0; r < 4; r++) {
        const int row  = row0 + r;
        const int base = row * 256;      // float4 index
        float4 A[8], C[8];
#pragma unroll
        for (int g = 0; g < 8; g++) {
            A[g] = __ldcs(&xt4[base + g * 32 + lane]);
            C[g] = __ldcs(&xi4[base + g * 32 + lane]);
        }
        float sa = 0.f, saa = 0.f, sc = 0.f, scc = 0.f;
#pragma unroll
        for (int g = 0; g < 8; g++) {
            sa += A[g].x; saa = fmaf(A[g].x, A[g].x, saa);
            sa += A[g].y; saa = fmaf(A[g].y, A[g].y, saa);
            sa += A[g].z; saa = fmaf(A[g].z, A[g].z, saa);
            sa += A[g].w; saa = fmaf(A[g].w, A[g].w, saa);
            sc += C[g].x; scc = fmaf(C[g].x, C[g].x, scc);
            sc += C[g].y; scc = fmaf(C[g].y, C[g].y, scc);
            sc += C[g].z; scc = fmaf(C[g].z, C[g].z, scc);
            sc += C[g].w; scc = fmaf(C[g].w, C[g].w, scc);
        }
        sa = bfly(sa); saa = bfly(saa); sc = bfly(sc); scc = bfly(scc);

        const float mut = sa * (1.f / 1024.f);
        const float rt  = rsqrtf(fmaxf(saa * (1.f / 1024.f) - mut * mut, 0.f) + 1e-5f);
        const float mui = sc * (1.f / 1024.f);
        const float ri  = rsqrtf(fmaxf(scc * (1.f / 1024.f) - mui * mui, 0.f) + 1e-5f);
        if (lane == 0) g_rowstats[row] = make_float4(mut, rt, mui, ri);

        const float nmt = -rt * mut, nmi = -ri * mui;
        float tt = 0.f, ii = 0.f, ti = 0.f;
#pragma unroll
        for (int g = 0; g < 8; g++) {
            const int o = g * 128 + lane * 4;
            const float4 w_t = *reinterpret_cast<float4*>(&sm[o]);
            const float4 b_t = *reinterpret_cast<float4*>(&sm[1024 + o]);
            const float4 w_i = *reinterpret_cast<float4*>(&sm[2048 + o]);
            const float4 b_i = *reinterpret_cast<float4*>(&sm[3072 + o]);

            float f, h2, tn, in;
            f  = fmaf(A[g].x, rt, nmt);  tn = fmaf(f, w_t.x, b_t.x);
            h2 = fmaf(C[g].x, ri, nmi);  in = fmaf(h2, w_i.x, b_i.x);
            tt = fmaf(tn, tn, tt); ii = fmaf(in, in, ii); ti = fmaf(tn, in, ti);
            vt[g].x += tn; vi[g].x += in;

            f  = fmaf(A[g].y, rt, nmt);  tn = fmaf(f, w_t.y, b_t.y);
            h2 = fmaf(C[g].y, ri, nmi);  in = fmaf(h2, w_i.y, b_i.y);
            tt = fmaf(tn, tn, tt); ii = fmaf(in, in, ii); ti = fmaf(tn, in, ti);
            vt[g].y += tn; vi[g].y += in;

            f  = fmaf(A[g].z, rt, nmt);  tn = fmaf(f, w_t.z, b_t.z);
            h2 = fmaf(C[g].z, ri, nmi);  in = fmaf(h2, w_i.z, b_i.z);
            tt = fmaf(tn, tn, tt); ii = fmaf(in, in, ii); ti = fmaf(tn, in, ti);
            vt[g].z += tn; vi[g].z += in;

            f  = fmaf(A[g].w, rt, nmt);  tn = fmaf(f, w_t.w, b_t.w);
            h2 = fmaf(C[g].w, ri, nmi);  in = fmaf(h2, w_i.w, b_i.w);
            tt = fmaf(tn, tn, tt); ii = fmaf(in, in, ii); ti = fmaf(tn, in, ti);
            vt[g].w += tn; vi[g].w += in;
        }
        tt = bfly(tt); ii = bfly(ii); ti = bfly(ti);
        sim_acc += ti / (fmaxf(sqrtf(tt), 1e-6f) * fmaxf(sqrtf(ii), 1e-6f));
    }

    if (lane == 0) s_sim[warp] = sim_acc;
    __syncthreads();    // weights no longer needed; reuse sm as 4 combine slices

    float* slice = sm + (warp & 3) * 2048;
    if (warp < 4) {
#pragma unroll
        for (int g = 0; g < 8; g++) {
            *reinterpret_cast<float4*>(&slice[g * 128 + lane * 4])        = vt[g];
            *reinterpret_cast<float4*>(&slice[1024 + g * 128 + lane * 4]) = vi[g];
        }
    }
    __syncthreads();
    if (warp >= 4) {
#pragma unroll
        for (int g = 0; g < 8; g++) {
            float4* p = reinterpret_cast<float4*>(&slice[g * 128 + lane * 4]);
            float4 v = *p;
            v.x += vt[g].x; v.y += vt[g].y; v.z += vt[g].z; v.w += vt[g].w;
            *p = v;
            float4* q = reinterpret_cast<float4*>(&slice[1024 + g * 128 + lane * 4]);
            float4 u = *q;
            u.x += vi[g].x; u.y += vi[g].y; u.z += vi[g].z; u.w += vi[g].w;
            *q = u;
        }
    }
    __syncthreads();
    for (int j = tid; j < 2048; j += 256) {
        g_partial[blk * 2048 + j] = (sm[j] + sm[2048 + j]) + (sm[4096 + j] + sm[6144 + j]);
    }
    if (tid == 0) {
        float s = 0.f;
#pragma unroll
        for (int w = 0; w < 8; w++) s += s_sim[w];
        g_simpart[blk] = s;
    }
}

// ---------------- pass 2: fold 64 partials per batch (deterministic) --------
__global__ void __launch_bounds__(256) k_reduce()
{
    __shared__ float tmp[2];
    const int blk  = blockIdx.x;               // 64 blocks
    const int b    = blk >> 3;                 // 8 blocks per batch
    const int slot = (blk & 7) * 256 + threadIdx.x;   // 0..2047

    if ((blk & 7) == 0) {                      // block-uniform branch
        float v = (threadIdx.x < 64) ? g_simpart[b * 64 + threadIdx.x] : 0.f;
        v = bfly(v);
        if (threadIdx.x < 64 && (threadIdx.x & 31) == 0) tmp[threadIdx.x >> 5] = v;
        __syncthreads();
        if (threadIdx.x == 0) g_globalsim[b] = (tmp[0] + tmp[1]) * (1.f / (float)Sc);
    }

    float s = 0.f;
#pragma unroll 8
    for (int p = 0; p < 64; p++)
        s += g_partial[(b * 64 + p) * 2048 + slot];
    g_sums[b * 2048 + slot] = s * (1.f / (float)Sc);
}

// ---------------- pass 3: warp-per-output gate GEMV -------------------------
__global__ void __launch_bounds__(256) k_gates(
    const float* __restrict__ Wa, const float* __restrict__ Wab,
    const float* __restrict__ Wq, const float* __restrict__ Wqb,
    const float* __restrict__ simw, const float* __restrict__ simb)
{
    const int warp = threadIdx.x >> 5, lane = threadIdx.x & 31;
    const int ow = blockIdx.x * 8 + warp;      // 0..8191
    const int b  = ow >> 10;
    const int hk = ow & 1023;                  // h*256 + k
    const int k  = hk & 255;

    const float4* wa = reinterpret_cast<const float4*>(Wa + (size_t)hk * 1024);
    const float4* wq = reinterpret_cast<const float4*>(Wq + (size_t)hk * 1024);
    const float4* tg = reinterpret_cast<const float4*>(g_sums + b * 2048);
    const float4* ig = reinterpret_cast<const float4*>(g_sums + b * 2048 + 1024);

    float da = 0.f, dq = 0.f;
#pragma unroll
    for (int g = 0; g < 8; g++) {
        const float4 a = wa[g * 32 + lane], t = tg[g * 32 + lane];
        const float4 q = wq[g * 32 + lane], i = ig[g * 32 + lane];
        da = fmaf(a.x, t.x, da); da = fmaf(a.y, t.y, da);
        da = fmaf(a.z, t.z, da); da = fmaf(a.w, t.w, da);
        dq = fmaf(q.x, i.x, dq); dq = fmaf(q.y, i.y, dq);
        dq = fmaf(q.z, i.z, dq); dq = fmaf(q.w, i.w, dq);
    }
    da = bfly(da); dq = bfly(dq);
    if (lane == 0) {
        const float gate = da + Wab[hk] + dq + Wqb[hk]
                         + g_globalsim[b] * simw[k] + simb[k];
        g_gates[b * 1024 + hk] = fmaxf(gate, 0.f);
    }
}

// ---------------- pass 4: final scalar gate per batch -----------------------
__global__ void __launch_bounds__(256) k_fc(
    const float* __restrict__ fcw, const float* __restrict__ fcb)
{
    const int b = blockIdx.x, tid = threadIdx.x;
    float acc = 0.f;
#pragma unroll
    for (int k = tid; k < 1024; k += 256) acc += g_gates[b * 1024 + k] * fcw[k];
    __shared__ float sh[8];
    acc = bfly(acc);
    if ((tid & 31) == 0) sh[tid >> 5] = acc;
    __syncthreads();
    if (tid == 0) {
        float s = 0.f;
#pragma unroll
        for (int w = 0; w < 8; w++) s += sh[w];
        g_gate[b] = 1.0f / (1.0f + expf(-(s + fcb[0])));
    }
}

// ---------------- pass 5: out = g*LN(t) + (1-g)*LN(i) -----------------------
__global__ void __launch_bounds__(256) k_out(
    const float* __restrict__ xt, const float* __restrict__ xi,
    const float* __restrict__ ltw, const float* __restrict__ ltb,
    const float* __restrict__ liw, const float* __restrict__ lib,
    float* __restrict__ out)
{
    const int t = threadIdx.x;
    const float4 wt = reinterpret_cast<const float4*>(ltw)[t];
    const float4 bt = reinterpret_cast<const float4*>(ltb)[t];
    const float4 wi = reinterpret_cast<const float4*>(liw)[t];
    const float4 bi = reinterpret_cast<const float4*>(lib)[t];
    const float4* xt4 = reinterpret_cast<const float4*>(xt);
    const float4* xi4 = reinterpret_cast<const float4*>(xi);
    float4* o4 = reinterpret_cast<float4*>(out);

    const int row0 = blockIdx.x * 4;
#pragma unroll
    for (int r = 0; r < 4; r++) {
        const int row = row0 + r;
        const float4 rs = g_rowstats[row];
        const float g  = g_gate[row >> 11];
        const float gm = 1.0f - g;
        const int idx  = row * 256 + t;
        const float4 a = __ldcs(&xt4[idx]);
        const float4 c = __ldcs(&xi4[idx]);
        float4 o;
        o.x = g * ((a.x - rs.x) * rs.y * wt.x + bt.x) + gm * ((c.x - rs.z) * rs.w * wi.x + bi.x);
        o.y = g * ((a.y - rs.x) * rs.y * wt.y + bt.y) + gm * ((c.y - rs.z) * rs.w * wi.y + bi.y);
        o.z = g * ((a.z - rs.x) * rs.y * wt.z + bt.z) + gm * ((c.z - rs.z) * rs.w * wi.z + bi.z);
        o.w = g * ((a.w - rs.x) * rs.y * wt.w + bt.w) + gm * ((c.w - rs.z) * rs.w * wi.w + bi.w);
        __stcs(&o4[idx], o);
    }
}

// ---------------- launch -----------------------------------------------------
extern "C" void kernel_launch(void* const* d_in, const int* in_sizes, int n_in,
                              void* d_out, int out_size)
{
    const float* xt   = (const float*)d_in[0];
    const float* xi   = (const float*)d_in[1];
    const float* ltw  = (const float*)d_in[2];
    const float* ltb  = (const float*)d_in[3];
    const float* liw  = (const float*)d_in[4];
    const float* lib  = (const float*)d_in[5];
    const float* Wa   = (const float*)d_in[6];
    const float* Wab  = (const float*)d_in[7];
    const float* Wq   = (const float*)d_in[8];
    const float* Wqb  = (const float*)d_in[9];
    const float* simw = (const float*)d_in[10];
    const float* simb = (const float*)d_in[11];
    const float* fcw  = (const float*)d_in[12];
    const float* fcb  = (const float*)d_in[13];
    float* out = (float*)d_out;

    k_stats <<<NBLK, 256>>>(xt, xi, ltw, ltb, liw, lib);
    k_reduce<<<64, 256>>>();
    k_gates <<<1024, 256>>>(Wa, Wab, Wq, Wqb, simw, simb);
    k_fc    <<<Bc, 256>>>(fcw, fcb);
    k_out   <<<(Bc * Sc) / 4, 256>>>(xt, xi, ltw, ltb, liw, lib, out);
}